// round 7
// baseline (speedup 1.0000x reference)
#include <cuda_runtime.h>

#define N_NODES 50000
#define N_EDGES 800000
#define HID     128
#define NH      8
#define HD      16
#define NB_SCAN 196   // ceil(N_NODES/256)
#define CAP     64    // edges per softmax chunk (deg ~ Poisson(16); >64 ~ never)

// ---------------- scratch (device globals; no allocation allowed) ----------------
__device__ float g_wfoldT[16 * HID];    // [c][k] transposed folded weights
__device__ float g_bfold[16];
__device__ float g_alpha[N_NODES * 16]; // [n][c]: 0..7 alpha_src, 8..15 alpha_dst
__device__ int   g_is64;
__device__ int   g_deg[N_NODES];
__device__ int   g_ptr[N_NODES];        // CSR start per destination node
__device__ int   g_cursor[N_NODES];
__device__ int   g_bsum[NB_SCAN];
__device__ int   g_boff[NB_SCAN];
__device__ int   g_csrc[N_EDGES];       // CSR: source node of each incoming edge

// ---------------- K0: detect edge_index dtype ----------------
// int64 data: every 8-byte word is a node id in [0,N). int32 data: the hi half of
// an 8-byte read is ~uniform[0,N); 64 consecutive zero-hi words has prob ~0.
__global__ void detect_kernel(const void* __restrict__ ei) {
    if (threadIdx.x != 0) return;
    const long long* p = (const long long*)ei;
    int ok = 1;
    for (int i = 0; i < 64; i++) {
        long long v = p[i];
        if (v < 0 || v >= N_NODES) { ok = 0; break; }
    }
    g_is64 = ok;
}

// ---------------- K1: zero degree histogram ----------------
__global__ void zdeg_kernel() {
    int i = blockIdx.x * blockDim.x + threadIdx.x;
    if (i < N_NODES) g_deg[i] = 0;
}

// ---------------- K2: degree histogram (reads ei directly) ----------------
__global__ void hist_kernel(const void* __restrict__ ei) {
    int e = blockIdx.x * blockDim.x + threadIdx.x;
    if (e >= N_EDGES) return;
    int c;
    if (g_is64) c = (int)__ldg((const long long*)ei + N_EDGES + e);
    else        c = __ldg((const int*)ei + N_EDGES + e);
    atomicAdd(g_deg + c, 1);
}

// ---------------- K3..K5: exclusive scan of deg -> ptr ----------------
__global__ void scan1_kernel() {
    __shared__ int s[256];
    int i = blockIdx.x * 256 + threadIdx.x;
    int v = (i < N_NODES) ? g_deg[i] : 0;
    s[threadIdx.x] = v;
    __syncthreads();
#pragma unroll
    for (int off = 1; off < 256; off <<= 1) {
        int t = (threadIdx.x >= off) ? s[threadIdx.x - off] : 0;
        __syncthreads();
        s[threadIdx.x] += t;
        __syncthreads();
    }
    if (i < N_NODES) g_ptr[i] = s[threadIdx.x] - v;   // exclusive
    if (threadIdx.x == 255) g_bsum[blockIdx.x] = s[255];
}

__global__ void scan2_kernel() {
    __shared__ int s[256];
    int v = (threadIdx.x < NB_SCAN) ? g_bsum[threadIdx.x] : 0;
    s[threadIdx.x] = v;
    __syncthreads();
#pragma unroll
    for (int off = 1; off < 256; off <<= 1) {
        int t = (threadIdx.x >= off) ? s[threadIdx.x - off] : 0;
        __syncthreads();
        s[threadIdx.x] += t;
        __syncthreads();
    }
    if (threadIdx.x < NB_SCAN) g_boff[threadIdx.x] = s[threadIdx.x] - v;
}

__global__ void scan3_kernel() {
    int i = blockIdx.x * blockDim.x + threadIdx.x;
    if (i >= N_NODES) return;
    int p = g_ptr[i] + g_boff[i >> 8];
    g_ptr[i] = p;
    g_cursor[i] = p;
}

// ---------------- K6: scatter edges into CSR (reads ei directly) ----------------
__global__ void scatter_kernel(const void* __restrict__ ei) {
    int e = blockIdx.x * blockDim.x + threadIdx.x;
    if (e >= N_EDGES) return;
    int r, c;
    if (g_is64) {
        const long long* p = (const long long*)ei;
        r = (int)__ldg(p + e);
        c = (int)__ldg(p + N_EDGES + e);
    } else {
        const int* p = (const int*)ei;
        r = __ldg(p + e);
        c = __ldg(p + N_EDGES + e);
    }
    int pos = atomicAdd(g_cursor + c, 1);
    g_csrc[pos] = r;
}

// ---------------- K7: fold node_w/node_b with att_w (store transposed) ----------------
// alpha_src[n,h] = x[n,:] . (node_w[:, h*32:h*32+16] @ att_w[h,0:16]) -> 128x16 fold.
__global__ void fold_kernel(const float* __restrict__ node_w,
                            const float* __restrict__ node_b,
                            const float* __restrict__ att_w) {
    int tid = threadIdx.x;
    for (int i = tid; i < HID * 16; i += blockDim.x) {
        int k = i >> 4;
        int c = i & 15;
        int h = c & 7;
        int off = (c < 8) ? 0 : HD;
        float s = 0.f;
#pragma unroll
        for (int d = 0; d < HD; d++)
            s += node_w[k * (2 * HID) + h * (2 * HD) + off + d] *
                 att_w[h * (2 * HD) + off + d];
        g_wfoldT[c * HID + k] = s;
    }
    if (tid < 16) {
        int c = tid;
        int h = c & 7;
        int off = (c < 8) ? 0 : HD;
        float s = 0.f;
#pragma unroll
        for (int d = 0; d < HD; d++)
            s += node_b[h * (2 * HD) + off + d] * att_w[h * (2 * HD) + off + d];
        g_bfold[c] = s;
    }
}

// ---------------- K8: alpha[n][c] = x[n,:] . wfoldT[c,:] + bfold[c] ----------------
__global__ void alpha_kernel(const float* __restrict__ x) {
    int g = blockIdx.x * blockDim.x + threadIdx.x;   // N_NODES*16 threads
    int n = g >> 4;
    int c = g & 15;
    if (n >= N_NODES) return;
    const float4* xr = (const float4*)(x + (size_t)n * HID);
    const float4* wr = (const float4*)(g_wfoldT + c * HID);
    float acc = g_bfold[c];
#pragma unroll 8
    for (int k = 0; k < HID / 4; k++) {
        float4 xv = __ldg(xr + k);
        float4 wv = wr[k];
        acc += xv.x * wv.x + xv.y * wv.y + xv.z * wv.z + xv.w * wv.w;
    }
    g_alpha[g] = acc;
}

// ---------------- K9: fused GAT, warp per node, 3 phases per chunk ----------------
// P1: lanes stride edges; gather alpha, compute 8 leaky scores (regs), stash csrc
//     in smem; xor-reduce 8-head max (floored at 0, matching reference).
// P2: exp own scores (regs), write weights to smem (stride-9, conflict-free),
//     xor-reduce 8 sums.
// P3: serial edge loop, unrolled x4: smem csrc + smem weight + ONE float4 x gather.
// Chunked (CAP) with flash rescale at chunk boundaries for unbounded degree.
__global__ void __launch_bounds__(256)
gat_kernel(const float* __restrict__ x, float* __restrict__ out) {
    __shared__ int   s_src[8][CAP];
    __shared__ float s_w[8][CAP * 9];    // [jj*9 + h], stride 9 => conflict-free

    int warp = (blockIdx.x * blockDim.x + threadIdx.x) >> 5;
    int wid  = (threadIdx.x >> 5);
    int lane = threadIdx.x & 31;
    if (warp >= N_NODES) return;
    int n    = warp;
    int hh   = lane >> 2;                // head for my 4 dims

    int base = g_ptr[n];
    int deg  = g_deg[n];

    // dst alpha: every lane holds all 8 (L1-broadcast float4 loads)
    float ad8[NH];
    {
        float4 d0 = *(const float4*)(g_alpha + n * 16 + 8);
        float4 d1 = *(const float4*)(g_alpha + n * 16 + 12);
        ad8[0]=d0.x; ad8[1]=d0.y; ad8[2]=d0.z; ad8[3]=d0.w;
        ad8[4]=d1.x; ad8[5]=d1.y; ad8[6]=d1.z; ad8[7]=d1.w;
    }

    float m[NH], sum[NH];
#pragma unroll
    for (int h = 0; h < NH; h++) { m[h] = 0.f; sum[h] = 0.f; }  // 0-floor like ref
    float ax = 0.f, ay = 0.f, az = 0.f, aw = 0.f;

    for (int c0 = 0; c0 < deg; c0 += CAP) {
        int cnt = min(CAP, deg - c0);

        // ---- Phase 1: lane-parallel scores ----
        float s_loc[CAP / 32][NH];
        float mx[NH];
#pragma unroll
        for (int h = 0; h < NH; h++) mx[h] = -1e30f;
#pragma unroll
        for (int t = 0; t < CAP / 32; t++) {
            int jj = t * 32 + lane;
            if (jj < cnt) {
                int r = __ldg(g_csrc + base + c0 + jj);
                s_src[wid][jj] = r;
                float4 a0 = *(const float4*)(g_alpha + r * 16);
                float4 a1 = *(const float4*)(g_alpha + r * 16 + 4);
                float sa[NH] = {a0.x, a0.y, a0.z, a0.w, a1.x, a1.y, a1.z, a1.w};
#pragma unroll
                for (int h = 0; h < NH; h++) {
                    float s = sa[h] + ad8[h];
                    s = (s >= 0.f) ? s : 0.2f * s;
                    s_loc[t][h] = s;
                    mx[h] = fmaxf(mx[h], s);
                }
            } else {
#pragma unroll
                for (int h = 0; h < NH; h++) s_loc[t][h] = -1e30f;
            }
        }
        // xor-reduce max over lanes (all lanes end with full result)
#pragma unroll
        for (int off = 16; off >= 1; off >>= 1)
#pragma unroll
            for (int h = 0; h < NH; h++)
                mx[h] = fmaxf(mx[h], __shfl_xor_sync(0xffffffffu, mx[h], off));

        // combine with running max; rescale prior chunks (c0>0 only, ~never)
        if (c0 > 0) {
            float fh = 1.f;
#pragma unroll
            for (int h = 0; h < NH; h++) {
                float mn = fmaxf(m[h], mx[h]);
                float f  = __expf(m[h] - mn);
                sum[h] *= f;
                m[h] = mn;
                if (h == hh) fh = f;
            }
            ax *= fh; ay *= fh; az *= fh; aw *= fh;
        } else {
#pragma unroll
            for (int h = 0; h < NH; h++) m[h] = fmaxf(m[h], mx[h]);
        }

        // ---- Phase 2: exp own scores, stash weights, reduce sums ----
        float ps[NH];
#pragma unroll
        for (int h = 0; h < NH; h++) ps[h] = 0.f;
#pragma unroll
        for (int t = 0; t < CAP / 32; t++) {
            int jj = t * 32 + lane;
            if (jj < cnt) {
#pragma unroll
                for (int h = 0; h < NH; h++) {
                    float w = __expf(s_loc[t][h] - m[h]);
                    ps[h] += w;
                    s_w[wid][jj * 9 + h] = w;
                }
            }
        }
#pragma unroll
        for (int off = 16; off >= 1; off >>= 1)
#pragma unroll
            for (int h = 0; h < NH; h++)
                ps[h] += __shfl_xor_sync(0xffffffffu, ps[h], off);
#pragma unroll
        for (int h = 0; h < NH; h++) sum[h] += ps[h];

        __syncwarp();

        // ---- Phase 3: aggregate; 4 gathers in flight ----
        int j = 0;
        for (; j + 4 <= cnt; j += 4) {
            int r0 = s_src[wid][j + 0];
            int r1 = s_src[wid][j + 1];
            int r2 = s_src[wid][j + 2];
            int r3 = s_src[wid][j + 3];
            float w0 = s_w[wid][(j + 0) * 9 + hh];
            float w1 = s_w[wid][(j + 1) * 9 + hh];
            float w2 = s_w[wid][(j + 2) * 9 + hh];
            float w3 = s_w[wid][(j + 3) * 9 + hh];
            float4 v0 = *(const float4*)(x + (size_t)r0 * HID + 4 * lane);
            float4 v1 = *(const float4*)(x + (size_t)r1 * HID + 4 * lane);
            float4 v2 = *(const float4*)(x + (size_t)r2 * HID + 4 * lane);
            float4 v3 = *(const float4*)(x + (size_t)r3 * HID + 4 * lane);
            ax += w0 * v0.x + w1 * v1.x + w2 * v2.x + w3 * v3.x;
            ay += w0 * v0.y + w1 * v1.y + w2 * v2.y + w3 * v3.y;
            az += w0 * v0.z + w1 * v1.z + w2 * v2.z + w3 * v3.z;
            aw += w0 * v0.w + w1 * v1.w + w2 * v2.w + w3 * v3.w;
        }
        for (; j < cnt; j++) {
            int r0 = s_src[wid][j];
            float w0 = s_w[wid][j * 9 + hh];
            float4 v0 = *(const float4*)(x + (size_t)r0 * HID + 4 * lane);
            ax += w0 * v0.x; ay += w0 * v0.y; az += w0 * v0.z; aw += w0 * v0.w;
        }
        __syncwarp();
    }

    float inv = __fdividef(1.f, sum[hh] + 1e-10f);
    float4 o = make_float4(ax * inv, ay * inv, az * inv, aw * inv);
    *(float4*)(out + (size_t)n * HID + 4 * lane) = o;
}

// ---------------- K10: in-place out = out @ out_w + out_b (50000x128x128) ----------------
#define BM 128
#define BN 128
#define BK 16
#define TM 8
#define TN 8

__global__ void __launch_bounds__(256, 2)
out_gemm_kernel(const float* __restrict__ Wm,
                const float* __restrict__ bias,
                float* __restrict__ out) {
    __shared__ float As[BK][BM + 4];
    __shared__ float Bs[BK][BN];

    int tid = threadIdx.x;
    int tx = tid & 15;
    int ty = tid >> 4;
    int m0 = blockIdx.x * BM;

    float acc[TM][TN];
#pragma unroll
    for (int i = 0; i < TM; i++)
#pragma unroll
        for (int j = 0; j < TN; j++) acc[i][j] = 0.f;

    for (int k0 = 0; k0 < HID; k0 += BK) {
#pragma unroll
        for (int p = 0; p < 2; p++) {
            int fid = p * 256 + tid;
            int m = fid >> 2;
            int kq = fid & 3;
            int mg = m0 + m;
            float4 v = make_float4(0.f, 0.f, 0.f, 0.f);
            if (mg < N_NODES)
                v = *(const float4*)(out + (size_t)mg * HID + k0 + kq * 4);
            As[kq * 4 + 0][m] = v.x;
            As[kq * 4 + 1][m] = v.y;
            As[kq * 4 + 2][m] = v.z;
            As[kq * 4 + 3][m] = v.w;
        }
#pragma unroll
        for (int p = 0; p < 2; p++) {
            int idx4 = p * 256 + tid;
            int k = idx4 >> 5;
            int nq = idx4 & 31;
            *(float4*)&Bs[k][nq * 4] =
                *(const float4*)(Wm + (size_t)(k0 + k) * HID + nq * 4);
        }
        __syncthreads();

#pragma unroll
        for (int kk = 0; kk < BK; kk++) {
            float4 a0 = *(const float4*)&As[kk][ty * TM];
            float4 a1 = *(const float4*)&As[kk][ty * TM + 4];
            float4 b0 = *(const float4*)&Bs[kk][tx * TN];
            float4 b1 = *(const float4*)&Bs[kk][tx * TN + 4];
            float a[TM] = {a0.x, a0.y, a0.z, a0.w, a1.x, a1.y, a1.z, a1.w};
            float b[TN] = {b0.x, b0.y, b0.z, b0.w, b1.x, b1.y, b1.z, b1.w};
#pragma unroll
            for (int i = 0; i < TM; i++)
#pragma unroll
                for (int j = 0; j < TN; j++)
                    acc[i][j] += a[i] * b[j];
        }
        __syncthreads();
    }

#pragma unroll
    for (int i = 0; i < TM; i++) {
        int mg = m0 + ty * TM + i;
        if (mg < N_NODES) {
#pragma unroll
            for (int j = 0; j < TN; j += 4) {
                int nn = tx * TN + j;
                float4 o;
                o.x = acc[i][j + 0] + __ldg(bias + nn + 0);
                o.y = acc[i][j + 1] + __ldg(bias + nn + 1);
                o.z = acc[i][j + 2] + __ldg(bias + nn + 2);
                o.w = acc[i][j + 3] + __ldg(bias + nn + 3);
                *(float4*)(out + (size_t)mg * HID + nn) = o;
            }
        }
    }
}

// ---------------- launch: kernel launches ONLY ----------------
extern "C" void kernel_launch(void* const* d_in, const int* in_sizes, int n_in,
                              void* d_out, int out_size) {
    const float* x      = (const float*)d_in[0];
    const void*  ei     = d_in[1];
    const float* node_w = (const float*)d_in[2];
    const float* node_b = (const float*)d_in[3];
    const float* att_w  = (const float*)d_in[4];
    const float* out_w  = (const float*)d_in[5];
    const float* out_b  = (const float*)d_in[6];
    float*       out    = (float*)d_out;

    detect_kernel<<<1, 32>>>(ei);
    zdeg_kernel<<<NB_SCAN, 256>>>();
    hist_kernel<<<(N_EDGES + 255) / 256, 256>>>(ei);
    scan1_kernel<<<NB_SCAN, 256>>>();
    scan2_kernel<<<1, 256>>>();
    scan3_kernel<<<NB_SCAN, 256>>>();
    scatter_kernel<<<(N_EDGES + 255) / 256, 256>>>(ei);

    fold_kernel<<<1, 256>>>(node_w, node_b, att_w);
    alpha_kernel<<<(N_NODES * 16 + 255) / 256, 256>>>(x);

    gat_kernel<<<(N_NODES * 32 + 255) / 256, 256>>>(x, out);

    out_gemm_kernel<<<(N_NODES + BM - 1) / BM, 256>>>(out_w, out_b, out);
}